// round 6
// baseline (speedup 1.0000x reference)
#include <cuda_runtime.h>
#include <cstdint>

#define NN 50000
#define DD 64
#define MAXE 1600000
#define SCAN_B 256

// Scratch (device globals; no allocations allowed)
__device__ __align__(16) float g_h[NN * DD];       // layer-0 output
__device__ __align__(16) float g_Wt0[2 * DD * DD]; // [k][j] pre-transposed weights
__device__ __align__(16) float g_Wt1[2 * DD * DD];
__device__ int g_is64;                             // edge-index dtype flag
__device__ int g_deg[NN];                          // in-degree (by dst)
__device__ int g_rowptr[NN];                       // CSR row starts
__device__ int g_cur[NN];                          // fill cursors
__device__ int g_col[MAXE];                        // CSR column (src) indices
__device__ int g_src[MAXE];                        // decoded int32 src
__device__ int g_dst[MAXE];                        // decoded int32 dst
__device__ int g_bsum[(NN + SCAN_B - 1) / SCAN_B];
__device__ int g_boff[(NN + SCAN_B - 1) / SCAN_B];

// ---- dtype detect: int64 indices < 50000 have zero hi-words ----
__global__ void detect_dtype(const long long* __restrict__ ei) {
    long long acc = 0;
#pragma unroll
    for (int i = 0; i < 8; i++) acc |= (ei[i] >> 32);
    g_is64 = (acc == 0) ? 1 : 0;
}

// prep weights + zero degree counters in one launch (grid covers NN)
__global__ void setup_kernel(const float* __restrict__ Wl0, const float* __restrict__ Wr0,
                             const float* __restrict__ Wl1, const float* __restrict__ Wr1) {
    int i = blockIdx.x * blockDim.x + threadIdx.x;
    if (i < 2 * DD * DD) {
        int k = i >> 6;
        int j = i & 63;
        g_Wt0[i] = (k < DD) ? Wl0[j * DD + k] : Wr0[j * DD + (k - DD)];
        g_Wt1[i] = (k < DD) ? Wl1[j * DD + k] : Wr1[j * DD + (k - DD)];
    }
    if (i < NN) g_deg[i] = 0;
}

// Decode edge list to int32 + degree histogram, one pass.
__global__ void convert_count(const void* __restrict__ ei_raw, int E) {
    int e = blockIdx.x * blockDim.x + threadIdx.x;
    if (e >= E) return;
    int s, d;
    if (g_is64) {
        const long long* ei = (const long long*)ei_raw;
        s = (int)ei[e];
        d = (int)ei[E + e];
    } else {
        const int* ei = (const int*)ei_raw;
        s = ei[e];
        d = ei[E + e];
    }
    g_src[e] = s;
    g_dst[e] = d;
    atomicAdd(&g_deg[d], 1);
}

// exclusive scan, 3 kernels
__global__ void scan1() {
    __shared__ int sh[SCAN_B];
    int i = blockIdx.x * SCAN_B + threadIdx.x;
    int v = (i < NN) ? g_deg[i] : 0;
    sh[threadIdx.x] = v;
    __syncthreads();
#pragma unroll
    for (int off = 1; off < SCAN_B; off <<= 1) {
        int t = (threadIdx.x >= off) ? sh[threadIdx.x - off] : 0;
        __syncthreads();
        sh[threadIdx.x] += t;
        __syncthreads();
    }
    int incl = sh[threadIdx.x];
    if (i < NN) g_rowptr[i] = incl - v;
    if (threadIdx.x == SCAN_B - 1) g_bsum[blockIdx.x] = incl;
}

__global__ void scan2(int nblk) {
    __shared__ int sh[SCAN_B];
    int v = (threadIdx.x < nblk) ? g_bsum[threadIdx.x] : 0;
    sh[threadIdx.x] = v;
    __syncthreads();
#pragma unroll
    for (int off = 1; off < SCAN_B; off <<= 1) {
        int t = (threadIdx.x >= off) ? sh[threadIdx.x - off] : 0;
        __syncthreads();
        sh[threadIdx.x] += t;
        __syncthreads();
    }
    if (threadIdx.x < nblk) g_boff[threadIdx.x] = sh[threadIdx.x] - v;
}

__global__ void scan3() {
    int i = blockIdx.x * SCAN_B + threadIdx.x;
    if (i < NN) {
        int r = g_rowptr[i] + g_boff[blockIdx.x];
        g_rowptr[i] = r;
        g_cur[i] = r;
    }
}

__global__ void fill_csr(int E) {
    int e = blockIdx.x * blockDim.x + threadIdx.x;
    if (e >= E) return;
    int pos = atomicAdd(&g_cur[g_dst[e]], 1);
    g_col[pos] = g_src[e];
}

// ---- Fused layer: CSR mean-aggregation + GEMM + bias (+ReLU), one kernel ----
// Block = 256 threads = 64-node tile. Thread (m = t&63, q = t>>6) aggregates
// k-chunk [q*16, q*16+16) of node m0+m in registers (4 independent float4
// gathers per neighbor, 2-neighbor unroll -> 8 in flight), writes straight
// into sA[k][m] (conflict-free: warp = same q, consecutive m). Then standard
// 4x4-microtile GEMM over the two 64-k halves [agg | xin].
__global__ __launch_bounds__(256) void layer_kernel(const float* __restrict__ x,
                                                    int useH, int useW1,
                                                    const float* __restrict__ bias,
                                                    float* __restrict__ dout,
                                                    int writeH, int doRelu) {
    __shared__ __align__(16) float sA[64 * 64];  // [k][m]
    __shared__ __align__(16) float sB[64 * 64];  // [k][j]
    const float* xin = useH ? g_h : x;
    const float* Wt = useW1 ? g_Wt1 : g_Wt0;
    float* outp = writeH ? g_h : dout;

    int t = threadIdx.x;
    int m0 = blockIdx.x * 64;
    int m = t & 63;
    int q = t >> 6;
    int node = m0 + m;

    // ---- Phase A: aggregate neighbors (k-chunk q*16..q*16+15) ----
    float4 a0 = make_float4(0.f, 0.f, 0.f, 0.f), a1 = a0, a2 = a0, a3 = a0;
    int beg = 0, deg = 0;
    if (node < NN) { beg = g_rowptr[node]; deg = g_deg[node]; }
    const float* xq = xin + q * 16;
    int j = 0;
    for (; j + 2 <= deg; j += 2) {
        int s0 = __ldg(g_col + beg + j);
        int s1 = __ldg(g_col + beg + j + 1);
        const float4* r0 = reinterpret_cast<const float4*>(xq + (size_t)s0 * DD);
        const float4* r1 = reinterpret_cast<const float4*>(xq + (size_t)s1 * DD);
        float4 v00 = __ldg(r0), v01 = __ldg(r0 + 1), v02 = __ldg(r0 + 2), v03 = __ldg(r0 + 3);
        float4 v10 = __ldg(r1), v11 = __ldg(r1 + 1), v12 = __ldg(r1 + 2), v13 = __ldg(r1 + 3);
        a0.x += v00.x; a0.y += v00.y; a0.z += v00.z; a0.w += v00.w;
        a1.x += v01.x; a1.y += v01.y; a1.z += v01.z; a1.w += v01.w;
        a2.x += v02.x; a2.y += v02.y; a2.z += v02.z; a2.w += v02.w;
        a3.x += v03.x; a3.y += v03.y; a3.z += v03.z; a3.w += v03.w;
        a0.x += v10.x; a0.y += v10.y; a0.z += v10.z; a0.w += v10.w;
        a1.x += v11.x; a1.y += v11.y; a1.z += v11.z; a1.w += v11.w;
        a2.x += v12.x; a2.y += v12.y; a2.z += v12.z; a2.w += v12.w;
        a3.x += v13.x; a3.y += v13.y; a3.z += v13.z; a3.w += v13.w;
    }
    if (j < deg) {
        int s0 = __ldg(g_col + beg + j);
        const float4* r0 = reinterpret_cast<const float4*>(xq + (size_t)s0 * DD);
        float4 v00 = __ldg(r0), v01 = __ldg(r0 + 1), v02 = __ldg(r0 + 2), v03 = __ldg(r0 + 3);
        a0.x += v00.x; a0.y += v00.y; a0.z += v00.z; a0.w += v00.w;
        a1.x += v01.x; a1.y += v01.y; a1.z += v01.z; a1.w += v01.w;
        a2.x += v02.x; a2.y += v02.y; a2.z += v02.z; a2.w += v02.w;
        a3.x += v03.x; a3.y += v03.y; a3.z += v03.z; a3.w += v03.w;
    }
    float sc = 1.f / (float)max(deg, 1);
    {
        int kb = q * 16;
        sA[(kb + 0) * 64 + m] = a0.x * sc;  sA[(kb + 1) * 64 + m] = a0.y * sc;
        sA[(kb + 2) * 64 + m] = a0.z * sc;  sA[(kb + 3) * 64 + m] = a0.w * sc;
        sA[(kb + 4) * 64 + m] = a1.x * sc;  sA[(kb + 5) * 64 + m] = a1.y * sc;
        sA[(kb + 6) * 64 + m] = a1.z * sc;  sA[(kb + 7) * 64 + m] = a1.w * sc;
        sA[(kb + 8) * 64 + m] = a2.x * sc;  sA[(kb + 9) * 64 + m] = a2.y * sc;
        sA[(kb + 10) * 64 + m] = a2.z * sc; sA[(kb + 11) * 64 + m] = a2.w * sc;
        sA[(kb + 12) * 64 + m] = a3.x * sc; sA[(kb + 13) * 64 + m] = a3.y * sc;
        sA[(kb + 14) * 64 + m] = a3.z * sc; sA[(kb + 15) * 64 + m] = a3.w * sc;
    }

    // ---- Phase B: GEMM over two 64-k halves ----
    int tx = t & 15;
    int ty = t >> 4;
    float acc[4][4];
#pragma unroll
    for (int i = 0; i < 4; i++)
#pragma unroll
        for (int jj = 0; jj < 4; jj++) acc[i][jj] = 0.f;

#pragma unroll
    for (int kt = 0; kt < 2; kt++) {
        // load B half (coalesced, conflict-free)
        const float4* Bsrc = reinterpret_cast<const float4*>(Wt + kt * 4096);
#pragma unroll
        for (int f = 0; f < 4; f++)
            reinterpret_cast<float4*>(sB)[f * 256 + t] = Bsrc[f * 256 + t];

        if (kt == 1) {
            // load xin rows for the self-term half
            const float* srcRow = xin + (size_t)node * DD;
            int kb = q * 16;
#pragma unroll
            for (int f = 0; f < 4; f++) {
                float4 v = make_float4(0.f, 0.f, 0.f, 0.f);
                if (node < NN)
                    v = *reinterpret_cast<const float4*>(srcRow + kb + f * 4);
                int k = kb + f * 4;
                sA[(k + 0) * 64 + m] = v.x;
                sA[(k + 1) * 64 + m] = v.y;
                sA[(k + 2) * 64 + m] = v.z;
                sA[(k + 3) * 64 + m] = v.w;
            }
        }
        __syncthreads();

#pragma unroll 8
        for (int k = 0; k < 64; k++) {
            float4 a = *reinterpret_cast<const float4*>(sA + k * 64 + ty * 4);
            float4 b = *reinterpret_cast<const float4*>(sB + k * 64 + tx * 4);
            acc[0][0] += a.x * b.x; acc[0][1] += a.x * b.y; acc[0][2] += a.x * b.z; acc[0][3] += a.x * b.w;
            acc[1][0] += a.y * b.x; acc[1][1] += a.y * b.y; acc[1][2] += a.y * b.z; acc[1][3] += a.y * b.w;
            acc[2][0] += a.z * b.x; acc[2][1] += a.z * b.y; acc[2][2] += a.z * b.z; acc[2][3] += a.z * b.w;
            acc[3][0] += a.w * b.x; acc[3][1] += a.w * b.y; acc[3][2] += a.w * b.z; acc[3][3] += a.w * b.w;
        }
        __syncthreads();
    }

    float4 bv = *reinterpret_cast<const float4*>(bias + tx * 4);
#pragma unroll
    for (int i = 0; i < 4; i++) {
        int row = m0 + ty * 4 + i;
        if (row >= NN) continue;
        float4 o;
        o.x = acc[i][0] + bv.x;
        o.y = acc[i][1] + bv.y;
        o.z = acc[i][2] + bv.z;
        o.w = acc[i][3] + bv.w;
        if (doRelu) {
            o.x = fmaxf(o.x, 0.f); o.y = fmaxf(o.y, 0.f);
            o.z = fmaxf(o.z, 0.f); o.w = fmaxf(o.w, 0.f);
        }
        *reinterpret_cast<float4*>(outp + (size_t)row * DD + tx * 4) = o;
    }
}

extern "C" void kernel_launch(void* const* d_in, const int* in_sizes, int n_in,
                              void* d_out, int out_size) {
    const float* x        = (const float*)d_in[0];
    const void* ei        = d_in[1];
    const float* Wl0      = (const float*)d_in[2];
    const float* bl0      = (const float*)d_in[3];
    const float* Wr0      = (const float*)d_in[4];
    const float* Wl1      = (const float*)d_in[5];
    const float* bl1      = (const float*)d_in[6];
    const float* Wr1      = (const float*)d_in[7];
    float* out = (float*)d_out;

    int E = in_sizes[1] / 2;

    int nblk = (NN + SCAN_B - 1) / SCAN_B;
    int edgeBlocks = (E + 255) / 256;
    int gemmBlocks = (NN + 63) / 64;

    detect_dtype<<<1, 1>>>((const long long*)ei);
    setup_kernel<<<(NN + 255) / 256, 256>>>(Wl0, Wr0, Wl1, Wr1);

    // CSR build (shared by both layers)
    convert_count<<<edgeBlocks, 256>>>(ei, E);
    scan1<<<nblk, SCAN_B>>>();
    scan2<<<1, SCAN_B>>>(nblk);
    scan3<<<nblk, SCAN_B>>>();
    fill_csr<<<edgeBlocks, 256>>>(E);

    // Fused layers
    layer_kernel<<<gemmBlocks, 256>>>(x, /*useH=*/0, /*useW1=*/0, bl0, out,
                                      /*writeH=*/1, /*doRelu=*/1);
    layer_kernel<<<gemmBlocks, 256>>>(x, /*useH=*/1, /*useW1=*/1, bl1, out,
                                      /*writeH=*/0, /*doRelu=*/0);
}

// round 7
// speedup vs baseline: 1.4382x; 1.4382x over previous
#include <cuda_runtime.h>
#include <cstdint>

#define NN 50000
#define DD 64
#define MAXE 1600000
#define SCAN_B 256

// Scratch (device globals; no allocations allowed)
__device__ __align__(16) float g_agg[NN * DD];     // normalized mean-agg buffer
__device__ __align__(16) float g_h[NN * DD];       // layer-0 output
__device__ __align__(16) float g_Wt0[2 * DD * DD]; // [k][j] pre-transposed weights
__device__ __align__(16) float g_Wt1[2 * DD * DD];
__device__ int g_is64;                             // edge-index dtype flag
__device__ int g_deg[NN];                          // in-degree (by dst)
__device__ int g_rowptr[NN];                       // CSR row starts
__device__ int g_cur[NN];                          // fill cursors
__device__ int g_col[MAXE];                        // CSR column (src) indices
__device__ __align__(16) int g_src[MAXE];          // decoded int32 src
__device__ __align__(16) int g_dst[MAXE];          // decoded int32 dst
__device__ int g_bsum[(NN + SCAN_B - 1) / SCAN_B];
__device__ int g_boff[(NN + SCAN_B - 1) / SCAN_B];

// ---- dtype detect: int64 indices < 50000 have zero hi-words ----
__global__ void detect_dtype(const long long* __restrict__ ei) {
    long long acc = 0;
#pragma unroll
    for (int i = 0; i < 8; i++) acc |= (ei[i] >> 32);
    g_is64 = (acc == 0) ? 1 : 0;
}

// prep weights + zero degree counters in one launch
__global__ void setup_kernel(const float* __restrict__ Wl0, const float* __restrict__ Wr0,
                             const float* __restrict__ Wl1, const float* __restrict__ Wr1) {
    int i = blockIdx.x * blockDim.x + threadIdx.x;
    if (i < 2 * DD * DD) {
        int k = i >> 6;
        int j = i & 63;
        g_Wt0[i] = (k < DD) ? Wl0[j * DD + k] : Wr0[j * DD + (k - DD)];
        g_Wt1[i] = (k < DD) ? Wl1[j * DD + k] : Wr1[j * DD + (k - DD)];
    }
    if (i < NN) g_deg[i] = 0;
}

// Decode edge list to int32 + degree histogram. 4 edges/thread, vector loads.
__global__ void convert_count(const void* __restrict__ ei_raw, int E) {
    int e0 = (blockIdx.x * blockDim.x + threadIdx.x) * 4;
    if (e0 >= E) return;
    int s[4], d[4];
    int nv = min(4, E - e0);
    if (g_is64) {
        const long long* ei = (const long long*)ei_raw;
        if (nv == 4 && ((e0 & 1) == 0)) {
            longlong2 s01 = *reinterpret_cast<const longlong2*>(ei + e0);
            longlong2 s23 = *reinterpret_cast<const longlong2*>(ei + e0 + 2);
            s[0] = (int)s01.x; s[1] = (int)s01.y; s[2] = (int)s23.x; s[3] = (int)s23.y;
            const long long* eid = ei + E + e0;
#pragma unroll
            for (int i = 0; i < 4; i++) d[i] = (int)eid[i];
        } else {
            for (int i = 0; i < nv; i++) { s[i] = (int)ei[e0 + i]; d[i] = (int)ei[E + e0 + i]; }
        }
    } else {
        const int* ei = (const int*)ei_raw;
        if (nv == 4 && ((E & 3) == 0)) {
            int4 sv = *reinterpret_cast<const int4*>(ei + e0);
            int4 dv = *reinterpret_cast<const int4*>(ei + E + e0);
            s[0] = sv.x; s[1] = sv.y; s[2] = sv.z; s[3] = sv.w;
            d[0] = dv.x; d[1] = dv.y; d[2] = dv.z; d[3] = dv.w;
        } else {
            for (int i = 0; i < nv; i++) { s[i] = ei[e0 + i]; d[i] = ei[E + e0 + i]; }
        }
    }
    if (nv == 4) {
        *reinterpret_cast<int4*>(g_src + e0) = make_int4(s[0], s[1], s[2], s[3]);
        *reinterpret_cast<int4*>(g_dst + e0) = make_int4(d[0], d[1], d[2], d[3]);
    } else {
        for (int i = 0; i < nv; i++) { g_src[e0 + i] = s[i]; g_dst[e0 + i] = d[i]; }
    }
#pragma unroll
    for (int i = 0; i < 4; i++)
        if (i < nv) atomicAdd(&g_deg[d[i]], 1);
}

// exclusive scan, 3 kernels
__global__ void scan1() {
    __shared__ int sh[SCAN_B];
    int i = blockIdx.x * SCAN_B + threadIdx.x;
    int v = (i < NN) ? g_deg[i] : 0;
    sh[threadIdx.x] = v;
    __syncthreads();
#pragma unroll
    for (int off = 1; off < SCAN_B; off <<= 1) {
        int t = (threadIdx.x >= off) ? sh[threadIdx.x - off] : 0;
        __syncthreads();
        sh[threadIdx.x] += t;
        __syncthreads();
    }
    int incl = sh[threadIdx.x];
    if (i < NN) g_rowptr[i] = incl - v;
    if (threadIdx.x == SCAN_B - 1) g_bsum[blockIdx.x] = incl;
}

__global__ void scan2(int nblk) {
    __shared__ int sh[SCAN_B];
    int v = (threadIdx.x < nblk) ? g_bsum[threadIdx.x] : 0;
    sh[threadIdx.x] = v;
    __syncthreads();
#pragma unroll
    for (int off = 1; off < SCAN_B; off <<= 1) {
        int t = (threadIdx.x >= off) ? sh[threadIdx.x - off] : 0;
        __syncthreads();
        sh[threadIdx.x] += t;
        __syncthreads();
    }
    if (threadIdx.x < nblk) g_boff[threadIdx.x] = sh[threadIdx.x] - v;
}

__global__ void scan3() {
    int i = blockIdx.x * SCAN_B + threadIdx.x;
    if (i < NN) {
        int r = g_rowptr[i] + g_boff[blockIdx.x];
        g_rowptr[i] = r;
        g_cur[i] = r;
    }
}

// CSR fill: 4 edges/thread, vector loads of the int32 copies.
__global__ void fill_csr(int E) {
    int e0 = (blockIdx.x * blockDim.x + threadIdx.x) * 4;
    if (e0 >= E) return;
    int nv = min(4, E - e0);
    if (nv == 4) {
        int4 sv = *reinterpret_cast<const int4*>(g_src + e0);
        int4 dv = *reinterpret_cast<const int4*>(g_dst + e0);
        int pos;
        pos = atomicAdd(&g_cur[dv.x], 1); g_col[pos] = sv.x;
        pos = atomicAdd(&g_cur[dv.y], 1); g_col[pos] = sv.y;
        pos = atomicAdd(&g_cur[dv.z], 1); g_col[pos] = sv.z;
        pos = atomicAdd(&g_cur[dv.w], 1); g_col[pos] = sv.w;
    } else {
        for (int i = 0; i < nv; i++) {
            int pos = atomicAdd(&g_cur[g_dst[e0 + i]], 1);
            g_col[pos] = g_src[e0 + i];
        }
    }
}

// ---- pull-style aggregation: 16 threads per node, atomic-free, MLP=8 ----
__global__ void aggregate(const float* __restrict__ x, int useH) {
    int gid = blockIdx.x * blockDim.x + threadIdx.x;
    int node = gid >> 4;
    int lane = gid & 15;
    if (node >= NN) return;
    const float* xin = useH ? g_h : x;

    int beg = g_rowptr[node];
    int deg = g_deg[node];

    float4 acc = make_float4(0.f, 0.f, 0.f, 0.f);
    int j = 0;
    for (; j + 8 <= deg; j += 8) {
        int idx[8];
#pragma unroll
        for (int i = 0; i < 8; i++) idx[i] = __ldg(g_col + beg + j + i);
        float4 v[8];
#pragma unroll
        for (int i = 0; i < 8; i++)
            v[i] = __ldg(reinterpret_cast<const float4*>(xin + (size_t)idx[i] * DD) + lane);
#pragma unroll
        for (int i = 0; i < 8; i++) {
            acc.x += v[i].x; acc.y += v[i].y; acc.z += v[i].z; acc.w += v[i].w;
        }
    }
    for (; j + 2 <= deg; j += 2) {
        int i0 = __ldg(g_col + beg + j);
        int i1 = __ldg(g_col + beg + j + 1);
        float4 v0 = __ldg(reinterpret_cast<const float4*>(xin + (size_t)i0 * DD) + lane);
        float4 v1 = __ldg(reinterpret_cast<const float4*>(xin + (size_t)i1 * DD) + lane);
        acc.x += v0.x; acc.y += v0.y; acc.z += v0.z; acc.w += v0.w;
        acc.x += v1.x; acc.y += v1.y; acc.z += v1.z; acc.w += v1.w;
    }
    for (; j < deg; j++) {
        int i0 = __ldg(g_col + beg + j);
        float4 v0 = __ldg(reinterpret_cast<const float4*>(xin + (size_t)i0 * DD) + lane);
        acc.x += v0.x; acc.y += v0.y; acc.z += v0.z; acc.w += v0.w;
    }
    float sc = 1.f / (float)max(deg, 1);
    acc.x *= sc; acc.y *= sc; acc.z *= sc; acc.w *= sc;
    reinterpret_cast<float4*>(g_agg + (size_t)node * DD)[lane] = acc;
}

// Fused: C[64 nodes][64 out] = A[64][128] * B[128][64] + bias (+ ReLU)
__global__ __launch_bounds__(256) void gemm_combine(const float* __restrict__ x,
                                                    int useH, int useW1,
                                                    const float* __restrict__ bias,
                                                    float* __restrict__ dout,
                                                    int writeH, int doRelu) {
    __shared__ __align__(16) float sA[64 * 64];  // [k][m]
    __shared__ __align__(16) float sB[64 * 64];  // [k][j]
    const float* xin = useH ? g_h : x;
    const float* Wt = useW1 ? g_Wt1 : g_Wt0;
    float* outp = writeH ? g_h : dout;

    int t = threadIdx.x;
    int m0 = blockIdx.x * 64;
    int m = t & 63;
    int q = t >> 6;
    int node = m0 + m;

    int tx = t & 15;
    int ty = t >> 4;

    float acc[4][4];
#pragma unroll
    for (int i = 0; i < 4; i++)
#pragma unroll
        for (int j = 0; j < 4; j++) acc[i][j] = 0.f;

#pragma unroll
    for (int kt = 0; kt < 2; kt++) {
        const float4* Bsrc = reinterpret_cast<const float4*>(Wt + kt * 4096);
#pragma unroll
        for (int f = 0; f < 4; f++)
            reinterpret_cast<float4*>(sB)[f * 256 + t] = Bsrc[f * 256 + t];

        const float* srcRow = (kt == 0) ? (g_agg + (size_t)node * DD)
                                        : (xin + (size_t)node * DD);
        int kbase = q * 16;
#pragma unroll
        for (int f = 0; f < 4; f++) {
            float4 v = make_float4(0.f, 0.f, 0.f, 0.f);
            if (node < NN)
                v = *reinterpret_cast<const float4*>(srcRow + kbase + f * 4);
            int k = kbase + f * 4;
            sA[(k + 0) * 64 + m] = v.x;
            sA[(k + 1) * 64 + m] = v.y;
            sA[(k + 2) * 64 + m] = v.z;
            sA[(k + 3) * 64 + m] = v.w;
        }
        __syncthreads();

#pragma unroll 8
        for (int k = 0; k < 64; k++) {
            float4 a = *reinterpret_cast<const float4*>(sA + k * 64 + ty * 4);
            float4 b = *reinterpret_cast<const float4*>(sB + k * 64 + tx * 4);
            acc[0][0] += a.x * b.x; acc[0][1] += a.x * b.y; acc[0][2] += a.x * b.z; acc[0][3] += a.x * b.w;
            acc[1][0] += a.y * b.x; acc[1][1] += a.y * b.y; acc[1][2] += a.y * b.z; acc[1][3] += a.y * b.w;
            acc[2][0] += a.z * b.x; acc[2][1] += a.z * b.y; acc[2][2] += a.z * b.z; acc[2][3] += a.z * b.w;
            acc[3][0] += a.w * b.x; acc[3][1] += a.w * b.y; acc[3][2] += a.w * b.z; acc[3][3] += a.w * b.w;
        }
        __syncthreads();
    }

    float4 bv = *reinterpret_cast<const float4*>(bias + tx * 4);
#pragma unroll
    for (int i = 0; i < 4; i++) {
        int row = m0 + ty * 4 + i;
        if (row >= NN) continue;
        float4 o;
        o.x = acc[i][0] + bv.x;
        o.y = acc[i][1] + bv.y;
        o.z = acc[i][2] + bv.z;
        o.w = acc[i][3] + bv.w;
        if (doRelu) {
            o.x = fmaxf(o.x, 0.f); o.y = fmaxf(o.y, 0.f);
            o.z = fmaxf(o.z, 0.f); o.w = fmaxf(o.w, 0.f);
        }
        *reinterpret_cast<float4*>(outp + (size_t)row * DD + tx * 4) = o;
    }
}

extern "C" void kernel_launch(void* const* d_in, const int* in_sizes, int n_in,
                              void* d_out, int out_size) {
    const float* x        = (const float*)d_in[0];
    const void* ei        = d_in[1];
    const float* Wl0      = (const float*)d_in[2];
    const float* bl0      = (const float*)d_in[3];
    const float* Wr0      = (const float*)d_in[4];
    const float* Wl1      = (const float*)d_in[5];
    const float* bl1      = (const float*)d_in[6];
    const float* Wr1      = (const float*)d_in[7];
    float* out = (float*)d_out;

    int E = in_sizes[1] / 2;

    int nblk = (NN + SCAN_B - 1) / SCAN_B;
    int edge4Blocks = ((E + 3) / 4 + 255) / 256;
    int aggBlocks = (NN * 16 + 255) / 256;
    int gemmBlocks = (NN + 63) / 64;

    detect_dtype<<<1, 1>>>((const long long*)ei);
    setup_kernel<<<(NN + 255) / 256, 256>>>(Wl0, Wr0, Wl1, Wr1);

    // CSR build (shared by both layers)
    convert_count<<<edge4Blocks, 256>>>(ei, E);
    scan1<<<nblk, SCAN_B>>>();
    scan2<<<1, SCAN_B>>>(nblk);
    scan3<<<nblk, SCAN_B>>>();
    fill_csr<<<edge4Blocks, 256>>>(E);

    // Layer 0
    aggregate<<<aggBlocks, 256>>>(x, /*useH=*/0);
    gemm_combine<<<gemmBlocks, 256>>>(x, /*useH=*/0, /*useW1=*/0, bl0, out,
                                      /*writeH=*/1, /*doRelu=*/1);

    // Layer 1
    aggregate<<<aggBlocks, 256>>>(x, /*useH=*/1);
    gemm_combine<<<gemmBlocks, 256>>>(x, /*useH=*/1, /*useW1=*/1, bl1, out,
                                      /*writeH=*/0, /*doRelu=*/0);
}

// round 8
// speedup vs baseline: 1.5048x; 1.0463x over previous
#include <cuda_runtime.h>
#include <cstdint>

#define NN 50000
#define DD 64
#define MAXE 1600000
#define SCAN_B 256
#define NBLK ((NN + SCAN_B - 1) / SCAN_B)

// Scratch (device globals; no allocations allowed)
__device__ __align__(16) float g_agg[NN * DD];     // normalized mean-agg buffer
__device__ __align__(16) float g_h[NN * DD];       // layer-0 output
__device__ __align__(16) float g_Wt0[2 * DD * DD]; // [k][j] pre-transposed weights
__device__ __align__(16) float g_Wt1[2 * DD * DD];
__device__ int g_is64;                             // edge-index dtype flag
__device__ int g_deg[NN];                          // in-degree (by dst)
__device__ int g_rowptr[NN];                       // CSR row starts
__device__ int g_cur[NN];                          // fill cursors
__device__ int g_col[MAXE];                        // CSR column (src) indices
__device__ int g_src[MAXE];                        // decoded int32 src
__device__ int g_dst[MAXE];                        // decoded int32 dst
__device__ int g_bsum[NBLK];                       // scan block sums

// prep weights + zero degree counters + dtype detect, one launch
__global__ void setup_kernel(const float* __restrict__ Wl0, const float* __restrict__ Wr0,
                             const float* __restrict__ Wl1, const float* __restrict__ Wr1,
                             const long long* __restrict__ ei) {
    int i = blockIdx.x * blockDim.x + threadIdx.x;
    if (i == 0) {
        // int64 indices < 50000 have zero hi-words; int32 reinterpreted doesn't
        long long acc = 0;
#pragma unroll
        for (int k = 0; k < 8; k++) acc |= (ei[k] >> 32);
        g_is64 = (acc == 0) ? 1 : 0;
    }
    if (i < 2 * DD * DD) {
        int k = i >> 6;
        int j = i & 63;
        g_Wt0[i] = (k < DD) ? Wl0[j * DD + k] : Wr0[j * DD + (k - DD)];
        g_Wt1[i] = (k < DD) ? Wl1[j * DD + k] : Wr1[j * DD + (k - DD)];
    }
    if (i < NN) g_deg[i] = 0;
}

// Decode edge list to int32 + degree histogram, one pass (scalar: known-good form).
__global__ void convert_count(const void* __restrict__ ei_raw, int E) {
    int e = blockIdx.x * blockDim.x + threadIdx.x;
    if (e >= E) return;
    int s, d;
    if (g_is64) {
        const long long* ei = (const long long*)ei_raw;
        s = (int)ei[e];
        d = (int)ei[E + e];
    } else {
        const int* ei = (const int*)ei_raw;
        s = ei[e];
        d = ei[E + e];
    }
    g_src[e] = s;
    g_dst[e] = d;
    atomicAdd(&g_deg[d], 1);
}

// scan step 1: per-block exclusive scan + block sums
__global__ void scan1() {
    __shared__ int sh[SCAN_B];
    int i = blockIdx.x * SCAN_B + threadIdx.x;
    int v = (i < NN) ? g_deg[i] : 0;
    sh[threadIdx.x] = v;
    __syncthreads();
#pragma unroll
    for (int off = 1; off < SCAN_B; off <<= 1) {
        int t = (threadIdx.x >= off) ? sh[threadIdx.x - off] : 0;
        __syncthreads();
        sh[threadIdx.x] += t;
        __syncthreads();
    }
    int incl = sh[threadIdx.x];
    if (i < NN) g_rowptr[i] = incl - v;
    if (threadIdx.x == SCAN_B - 1) g_bsum[blockIdx.x] = incl;
}

// scan step 2 (merged): each block redundantly prefix-sums the block sums
// below it (<=196 values in shared), applies the offset, writes cursors.
__global__ void scan_apply() {
    __shared__ int sh[NBLK];
    for (int k = threadIdx.x; k < NBLK; k += SCAN_B) sh[k] = g_bsum[k];
    __syncthreads();
    // thread 0 computes exclusive prefix for THIS block's offset only when
    // needed; cheaper: all threads cooperatively reduce the first blockIdx.x
    // entries via per-thread partial + shared combine. blockIdx.x <= 196, so
    // a simple serial sum by thread 0 into shared is fine (<200 adds).
    __shared__ int off;
    if (threadIdx.x == 0) {
        int a = 0;
        for (int k = 0; k < blockIdx.x; k++) a += sh[k];
        off = a;
    }
    __syncthreads();
    int i = blockIdx.x * SCAN_B + threadIdx.x;
    if (i < NN) {
        int r = g_rowptr[i] + off;
        g_rowptr[i] = r;
        g_cur[i] = r;
    }
}

// CSR fill from compact int32 copies.
__global__ void fill_csr(int E) {
    int e = blockIdx.x * blockDim.x + threadIdx.x;
    if (e >= E) return;
    int pos = atomicAdd(&g_cur[g_dst[e]], 1);
    g_col[pos] = g_src[e];
}

// ---- pull-style aggregation: 16 threads per node, atomic-free (R5 form) ----
__global__ void aggregate(const float* __restrict__ x, int useH) {
    int gid = blockIdx.x * blockDim.x + threadIdx.x;
    int node = gid >> 4;
    int lane = gid & 15;
    if (node >= NN) return;
    const float* xin = useH ? g_h : x;

    int beg = g_rowptr[node];
    int deg = g_deg[node];

    float4 acc = make_float4(0.f, 0.f, 0.f, 0.f);
    int j = 0;
    for (; j + 4 <= deg; j += 4) {
        int i0 = __ldg(g_col + beg + j + 0);
        int i1 = __ldg(g_col + beg + j + 1);
        int i2 = __ldg(g_col + beg + j + 2);
        int i3 = __ldg(g_col + beg + j + 3);
        float4 v0 = __ldg(reinterpret_cast<const float4*>(xin + (size_t)i0 * DD) + lane);
        float4 v1 = __ldg(reinterpret_cast<const float4*>(xin + (size_t)i1 * DD) + lane);
        float4 v2 = __ldg(reinterpret_cast<const float4*>(xin + (size_t)i2 * DD) + lane);
        float4 v3 = __ldg(reinterpret_cast<const float4*>(xin + (size_t)i3 * DD) + lane);
        acc.x += v0.x; acc.y += v0.y; acc.z += v0.z; acc.w += v0.w;
        acc.x += v1.x; acc.y += v1.y; acc.z += v1.z; acc.w += v1.w;
        acc.x += v2.x; acc.y += v2.y; acc.z += v2.z; acc.w += v2.w;
        acc.x += v3.x; acc.y += v3.y; acc.z += v3.z; acc.w += v3.w;
    }
    for (; j < deg; j++) {
        int i0 = __ldg(g_col + beg + j);
        float4 v0 = __ldg(reinterpret_cast<const float4*>(xin + (size_t)i0 * DD) + lane);
        acc.x += v0.x; acc.y += v0.y; acc.z += v0.z; acc.w += v0.w;
    }
    float sc = 1.f / (float)max(deg, 1);
    acc.x *= sc; acc.y *= sc; acc.z *= sc; acc.w *= sc;
    reinterpret_cast<float4*>(g_agg + (size_t)node * DD)[lane] = acc;
}

// Fused: C[64 nodes][64 out] = A[64][128] * B[128][64] + bias (+ ReLU)  (R5 form)
__global__ __launch_bounds__(256) void gemm_combine(const float* __restrict__ x,
                                                    int useH, int useW1,
                                                    const float* __restrict__ bias,
                                                    float* __restrict__ dout,
                                                    int writeH, int doRelu) {
    __shared__ __align__(16) float sA[64 * 64];  // [k][m]
    __shared__ __align__(16) float sB[64 * 64];  // [k][j]
    const float* xin = useH ? g_h : x;
    const float* Wt = useW1 ? g_Wt1 : g_Wt0;
    float* outp = writeH ? g_h : dout;

    int t = threadIdx.x;
    int m0 = blockIdx.x * 64;
    int m = t & 63;
    int q = t >> 6;
    int node = m0 + m;

    int tx = t & 15;
    int ty = t >> 4;

    float acc[4][4];
#pragma unroll
    for (int i = 0; i < 4; i++)
#pragma unroll
        for (int j = 0; j < 4; j++) acc[i][j] = 0.f;

#pragma unroll
    for (int kt = 0; kt < 2; kt++) {
        const float4* Bsrc = reinterpret_cast<const float4*>(Wt + kt * 4096);
#pragma unroll
        for (int f = 0; f < 4; f++)
            reinterpret_cast<float4*>(sB)[f * 256 + t] = Bsrc[f * 256 + t];

        const float* srcRow = (kt == 0) ? (g_agg + (size_t)node * DD)
                                        : (xin + (size_t)node * DD);
        int kbase = q * 16;
#pragma unroll
        for (int f = 0; f < 4; f++) {
            float4 v = make_float4(0.f, 0.f, 0.f, 0.f);
            if (node < NN)
                v = *reinterpret_cast<const float4*>(srcRow + kbase + f * 4);
            int k = kbase + f * 4;
            sA[(k + 0) * 64 + m] = v.x;
            sA[(k + 1) * 64 + m] = v.y;
            sA[(k + 2) * 64 + m] = v.z;
            sA[(k + 3) * 64 + m] = v.w;
        }
        __syncthreads();

#pragma unroll 8
        for (int k = 0; k < 64; k++) {
            float4 a = *reinterpret_cast<const float4*>(sA + k * 64 + ty * 4);
            float4 b = *reinterpret_cast<const float4*>(sB + k * 64 + tx * 4);
            acc[0][0] += a.x * b.x; acc[0][1] += a.x * b.y; acc[0][2] += a.x * b.z; acc[0][3] += a.x * b.w;
            acc[1][0] += a.y * b.x; acc[1][1] += a.y * b.y; acc[1][2] += a.y * b.z; acc[1][3] += a.y * b.w;
            acc[2][0] += a.z * b.x; acc[2][1] += a.z * b.y; acc[2][2] += a.z * b.z; acc[2][3] += a.z * b.w;
            acc[3][0] += a.w * b.x; acc[3][1] += a.w * b.y; acc[3][2] += a.w * b.z; acc[3][3] += a.w * b.w;
        }
        __syncthreads();
    }

    float4 bv = *reinterpret_cast<const float4*>(bias + tx * 4);
#pragma unroll
    for (int i = 0; i < 4; i++) {
        int row = m0 + ty * 4 + i;
        if (row >= NN) continue;
        float4 o;
        o.x = acc[i][0] + bv.x;
        o.y = acc[i][1] + bv.y;
        o.z = acc[i][2] + bv.z;
        o.w = acc[i][3] + bv.w;
        if (doRelu) {
            o.x = fmaxf(o.x, 0.f); o.y = fmaxf(o.y, 0.f);
            o.z = fmaxf(o.z, 0.f); o.w = fmaxf(o.w, 0.f);
        }
        *reinterpret_cast<float4*>(outp + (size_t)row * DD + tx * 4) = o;
    }
}

extern "C" void kernel_launch(void* const* d_in, const int* in_sizes, int n_in,
                              void* d_out, int out_size) {
    const float* x        = (const float*)d_in[0];
    const void* ei        = d_in[1];
    const float* Wl0      = (const float*)d_in[2];
    const float* bl0      = (const float*)d_in[3];
    const float* Wr0      = (const float*)d_in[4];
    const float* Wl1      = (const float*)d_in[5];
    const float* bl1      = (const float*)d_in[6];
    const float* Wr1      = (const float*)d_in[7];
    float* out = (float*)d_out;

    int E = in_sizes[1] / 2;

    int edgeBlocks = (E + 255) / 256;
    int aggBlocks = (NN * 16 + 255) / 256;
    int gemmBlocks = (NN + 63) / 64;

    setup_kernel<<<(NN + 255) / 256, 256>>>(Wl0, Wr0, Wl1, Wr1, (const long long*)ei);

    // CSR build (shared by both layers)
    convert_count<<<edgeBlocks, 256>>>(ei, E);
    scan1<<<NBLK, SCAN_B>>>();
    scan_apply<<<NBLK, SCAN_B>>>();
    fill_csr<<<edgeBlocks, 256>>>(E);

    // Layer 0
    aggregate<<<aggBlocks, 256>>>(x, /*useH=*/0);
    gemm_combine<<<gemmBlocks, 256>>>(x, /*useH=*/0, /*useW1=*/0, bl0, out,
                                      /*writeH=*/1, /*doRelu=*/1);

    // Layer 1
    aggregate<<<aggBlocks, 256>>>(x, /*useH=*/1);
    gemm_combine<<<gemmBlocks, 256>>>(x, /*useH=*/1, /*useW1=*/1, bl1, out,
                                      /*writeH=*/0, /*doRelu=*/0);
}

// round 9
// speedup vs baseline: 1.5329x; 1.0187x over previous
#include <cuda_runtime.h>
#include <cstdint>

#define NN 50000
#define DD 64
#define MAXE 1600000
#define SCAN_B 256
#define NBLK ((NN + SCAN_B - 1) / SCAN_B)

// Scratch (device globals; no allocations allowed)
__device__ __align__(16) float g_agg[NN * DD];     // normalized mean-agg buffer
__device__ __align__(16) float g_h[NN * DD];       // layer-0 output
__device__ __align__(16) float g_Wt0[2 * DD * DD]; // [k][j] pre-transposed weights
__device__ __align__(16) float g_Wt1[2 * DD * DD];
__device__ int g_is64;                             // edge-index dtype flag
__device__ int g_deg[NN];                          // in-degree (by dst)
__device__ int g_rowptr[NN];                       // CSR row starts
__device__ int g_col[MAXE];                        // CSR column (src) indices
__device__ int g_src[MAXE];                        // decoded int32 src
__device__ int g_dst[MAXE];                        // decoded int32 dst
__device__ int g_rank[MAXE];                       // within-bucket rank per edge
__device__ int g_bsum[NBLK];                       // scan block sums

// prep weights + zero degree counters + dtype detect, one launch
__global__ void setup_kernel(const float* __restrict__ Wl0, const float* __restrict__ Wr0,
                             const float* __restrict__ Wl1, const float* __restrict__ Wr1,
                             const long long* __restrict__ ei) {
    int i = blockIdx.x * blockDim.x + threadIdx.x;
    if (i == 0) {
        // int64 indices < 50000 have zero hi-words; int32 reinterpreted doesn't
        long long acc = 0;
#pragma unroll
        for (int k = 0; k < 8; k++) acc |= (ei[k] >> 32);
        g_is64 = (acc == 0) ? 1 : 0;
    }
    if (i < 2 * DD * DD) {
        int k = i >> 6;
        int j = i & 63;
        g_Wt0[i] = (k < DD) ? Wl0[j * DD + k] : Wr0[j * DD + (k - DD)];
        g_Wt1[i] = (k < DD) ? Wl1[j * DD + k] : Wr1[j * DD + (k - DD)];
    }
    if (i < NN) g_deg[i] = 0;
}

// Decode edge list to int32 + degree histogram + within-bucket rank, one pass.
// The atomicAdd return value IS the rank -> fill_csr needs no atomics.
__global__ void convert_count(const void* __restrict__ ei_raw, int E) {
    int e = blockIdx.x * blockDim.x + threadIdx.x;
    if (e >= E) return;
    int s, d;
    if (g_is64) {
        const long long* ei = (const long long*)ei_raw;
        s = (int)ei[e];
        d = (int)ei[E + e];
    } else {
        const int* ei = (const int*)ei_raw;
        s = ei[e];
        d = ei[E + e];
    }
    g_src[e] = s;
    g_dst[e] = d;
    g_rank[e] = atomicAdd(&g_deg[d], 1);
}

// scan step 1: per-block exclusive scan + block sums
__global__ void scan1() {
    __shared__ int sh[SCAN_B];
    int i = blockIdx.x * SCAN_B + threadIdx.x;
    int v = (i < NN) ? g_deg[i] : 0;
    sh[threadIdx.x] = v;
    __syncthreads();
#pragma unroll
    for (int off = 1; off < SCAN_B; off <<= 1) {
        int t = (threadIdx.x >= off) ? sh[threadIdx.x - off] : 0;
        __syncthreads();
        sh[threadIdx.x] += t;
        __syncthreads();
    }
    int incl = sh[threadIdx.x];
    if (i < NN) g_rowptr[i] = incl - v;
    if (threadIdx.x == SCAN_B - 1) g_bsum[blockIdx.x] = incl;
}

// scan step 2 (merged): every block runs the same parallel Hillis-Steele scan
// over the <=NBLK block sums in shared, then applies its exclusive offset.
__global__ void scan_apply() {
    __shared__ int sh[SCAN_B];
    int v = (threadIdx.x < NBLK) ? g_bsum[threadIdx.x] : 0;
    sh[threadIdx.x] = v;
    __syncthreads();
#pragma unroll
    for (int off = 1; off < SCAN_B; off <<= 1) {
        int t = (threadIdx.x >= off) ? sh[threadIdx.x - off] : 0;
        __syncthreads();
        sh[threadIdx.x] += t;
        __syncthreads();
    }
    // exclusive prefix at blockIdx.x = inclusive(blockIdx.x) - bsum(blockIdx.x)
    int off = (blockIdx.x > 0) ? sh[blockIdx.x - 1] : 0;
    int i = blockIdx.x * SCAN_B + threadIdx.x;
    if (i < NN)
        g_rowptr[i] += off;
}

// CSR fill: atomic-free via precomputed ranks.
__global__ void fill_csr(int E) {
    int e = blockIdx.x * blockDim.x + threadIdx.x;
    if (e >= E) return;
    g_col[g_rowptr[g_dst[e]] + g_rank[e]] = g_src[e];
}

// ---- pull-style aggregation: 16 threads per node, atomic-free (R5 form) ----
__global__ void aggregate(const float* __restrict__ x, int useH) {
    int gid = blockIdx.x * blockDim.x + threadIdx.x;
    int node = gid >> 4;
    int lane = gid & 15;
    if (node >= NN) return;
    const float* xin = useH ? g_h : x;

    int beg = g_rowptr[node];
    int deg = g_deg[node];

    float4 acc = make_float4(0.f, 0.f, 0.f, 0.f);
    int j = 0;
    for (; j + 4 <= deg; j += 4) {
        int i0 = __ldg(g_col + beg + j + 0);
        int i1 = __ldg(g_col + beg + j + 1);
        int i2 = __ldg(g_col + beg + j + 2);
        int i3 = __ldg(g_col + beg + j + 3);
        float4 v0 = __ldg(reinterpret_cast<const float4*>(xin + (size_t)i0 * DD) + lane);
        float4 v1 = __ldg(reinterpret_cast<const float4*>(xin + (size_t)i1 * DD) + lane);
        float4 v2 = __ldg(reinterpret_cast<const float4*>(xin + (size_t)i2 * DD) + lane);
        float4 v3 = __ldg(reinterpret_cast<const float4*>(xin + (size_t)i3 * DD) + lane);
        acc.x += v0.x; acc.y += v0.y; acc.z += v0.z; acc.w += v0.w;
        acc.x += v1.x; acc.y += v1.y; acc.z += v1.z; acc.w += v1.w;
        acc.x += v2.x; acc.y += v2.y; acc.z += v2.z; acc.w += v2.w;
        acc.x += v3.x; acc.y += v3.y; acc.z += v3.z; acc.w += v3.w;
    }
    for (; j < deg; j++) {
        int i0 = __ldg(g_col + beg + j);
        float4 v0 = __ldg(reinterpret_cast<const float4*>(xin + (size_t)i0 * DD) + lane);
        acc.x += v0.x; acc.y += v0.y; acc.z += v0.z; acc.w += v0.w;
    }
    float sc = 1.f / (float)max(deg, 1);
    acc.x *= sc; acc.y *= sc; acc.z *= sc; acc.w *= sc;
    reinterpret_cast<float4*>(g_agg + (size_t)node * DD)[lane] = acc;
}

// Fused: C[64 nodes][64 out] = A[64][128] * B[128][64] + bias (+ ReLU)  (R5 form)
__global__ __launch_bounds__(256) void gemm_combine(const float* __restrict__ x,
                                                    int useH, int useW1,
                                                    const float* __restrict__ bias,
                                                    float* __restrict__ dout,
                                                    int writeH, int doRelu) {
    __shared__ __align__(16) float sA[64 * 64];  // [k][m]
    __shared__ __align__(16) float sB[64 * 64];  // [k][j]
    const float* xin = useH ? g_h : x;
    const float* Wt = useW1 ? g_Wt1 : g_Wt0;
    float* outp = writeH ? g_h : dout;

    int t = threadIdx.x;
    int m0 = blockIdx.x * 64;
    int m = t & 63;
    int q = t >> 6;
    int node = m0 + m;

    int tx = t & 15;
    int ty = t >> 4;

    float acc[4][4];
#pragma unroll
    for (int i = 0; i < 4; i++)
#pragma unroll
        for (int j = 0; j < 4; j++) acc[i][j] = 0.f;

#pragma unroll
    for (int kt = 0; kt < 2; kt++) {
        const float4* Bsrc = reinterpret_cast<const float4*>(Wt + kt * 4096);
#pragma unroll
        for (int f = 0; f < 4; f++)
            reinterpret_cast<float4*>(sB)[f * 256 + t] = Bsrc[f * 256 + t];

        const float* srcRow = (kt == 0) ? (g_agg + (size_t)node * DD)
                                        : (xin + (size_t)node * DD);
        int kbase = q * 16;
#pragma unroll
        for (int f = 0; f < 4; f++) {
            float4 v = make_float4(0.f, 0.f, 0.f, 0.f);
            if (node < NN)
                v = *reinterpret_cast<const float4*>(srcRow + kbase + f * 4);
            int k = kbase + f * 4;
            sA[(k + 0) * 64 + m] = v.x;
            sA[(k + 1) * 64 + m] = v.y;
            sA[(k + 2) * 64 + m] = v.z;
            sA[(k + 3) * 64 + m] = v.w;
        }
        __syncthreads();

#pragma unroll 8
        for (int k = 0; k < 64; k++) {
            float4 a = *reinterpret_cast<const float4*>(sA + k * 64 + ty * 4);
            float4 b = *reinterpret_cast<const float4*>(sB + k * 64 + tx * 4);
            acc[0][0] += a.x * b.x; acc[0][1] += a.x * b.y; acc[0][2] += a.x * b.z; acc[0][3] += a.x * b.w;
            acc[1][0] += a.y * b.x; acc[1][1] += a.y * b.y; acc[1][2] += a.y * b.z; acc[1][3] += a.y * b.w;
            acc[2][0] += a.z * b.x; acc[2][1] += a.z * b.y; acc[2][2] += a.z * b.z; acc[2][3] += a.z * b.w;
            acc[3][0] += a.w * b.x; acc[3][1] += a.w * b.y; acc[3][2] += a.w * b.z; acc[3][3] += a.w * b.w;
        }
        __syncthreads();
    }

    float4 bv = *reinterpret_cast<const float4*>(bias + tx * 4);
#pragma unroll
    for (int i = 0; i < 4; i++) {
        int row = m0 + ty * 4 + i;
        if (row >= NN) continue;
        float4 o;
        o.x = acc[i][0] + bv.x;
        o.y = acc[i][1] + bv.y;
        o.z = acc[i][2] + bv.z;
        o.w = acc[i][3] + bv.w;
        if (doRelu) {
            o.x = fmaxf(o.x, 0.f); o.y = fmaxf(o.y, 0.f);
            o.z = fmaxf(o.z, 0.f); o.w = fmaxf(o.w, 0.f);
        }
        *reinterpret_cast<float4*>(outp + (size_t)row * DD + tx * 4) = o;
    }
}

extern "C" void kernel_launch(void* const* d_in, const int* in_sizes, int n_in,
                              void* d_out, int out_size) {
    const float* x        = (const float*)d_in[0];
    const void* ei        = d_in[1];
    const float* Wl0      = (const float*)d_in[2];
    const float* bl0      = (const float*)d_in[3];
    const float* Wr0      = (const float*)d_in[4];
    const float* Wl1      = (const float*)d_in[5];
    const float* bl1      = (const float*)d_in[6];
    const float* Wr1      = (const float*)d_in[7];
    float* out = (float*)d_out;

    int E = in_sizes[1] / 2;

    int edgeBlocks = (E + 255) / 256;
    int aggBlocks = (NN * 16 + 255) / 256;
    int gemmBlocks = (NN + 63) / 64;

    setup_kernel<<<(NN + 255) / 256, 256>>>(Wl0, Wr0, Wl1, Wr1, (const long long*)ei);

    // CSR build (shared by both layers)
    convert_count<<<edgeBlocks, 256>>>(ei, E);
    scan1<<<NBLK, SCAN_B>>>();
    scan_apply<<<NBLK, SCAN_B>>>();
    fill_csr<<<edgeBlocks, 256>>>(E);

    // Layer 0
    aggregate<<<aggBlocks, 256>>>(x, /*useH=*/0);
    gemm_combine<<<gemmBlocks, 256>>>(x, /*useH=*/0, /*useW1=*/0, bl0, out,
                                      /*writeH=*/1, /*doRelu=*/1);

    // Layer 1
    aggregate<<<aggBlocks, 256>>>(x, /*useH=*/1);
    gemm_combine<<<gemmBlocks, 256>>>(x, /*useH=*/1, /*useW1=*/1, bl1, out,
                                      /*writeH=*/0, /*doRelu=*/0);
}

// round 10
// speedup vs baseline: 1.6470x; 1.0744x over previous
#include <cuda_runtime.h>
#include <cstdint>

#define NN 50000
#define DD 64
#define MAXE 1600000
#define SCAN_B 256
#define NBLK ((NN + SCAN_B - 1) / SCAN_B)

// Scratch (device globals; no allocations allowed)
__device__ __align__(16) float g_agg[NN * DD];     // normalized mean-agg buffer
__device__ __align__(16) float g_h[NN * DD];       // layer-0 output
__device__ __align__(16) float g_Wt0[2 * DD * DD]; // [k][j] pre-transposed weights
__device__ __align__(16) float g_Wt1[2 * DD * DD];
__device__ int g_is64;                             // edge-index dtype flag
__device__ int g_deg[NN];                          // in-degree (by dst)
__device__ int g_rowptr[NN];                       // CSR row starts
__device__ int g_col[MAXE];                        // CSR column (src) indices
__device__ int g_src[MAXE];                        // decoded int32 src
__device__ int g_dst[MAXE];                        // decoded int32 dst
__device__ int g_rank[MAXE];                       // within-bucket rank per edge
__device__ int g_bsum[NBLK];                       // scan block sums

// prep weights + zero degree counters + dtype detect, one launch
__global__ void setup_kernel(const float* __restrict__ Wl0, const float* __restrict__ Wr0,
                             const float* __restrict__ Wl1, const float* __restrict__ Wr1,
                             const long long* __restrict__ ei) {
    int i = blockIdx.x * blockDim.x + threadIdx.x;
    if (i == 0) {
        long long acc = 0;
#pragma unroll
        for (int k = 0; k < 8; k++) acc |= (ei[k] >> 32);
        g_is64 = (acc == 0) ? 1 : 0;
    }
    if (i < 2 * DD * DD) {
        int k = i >> 6;
        int j = i & 63;
        g_Wt0[i] = (k < DD) ? Wl0[j * DD + k] : Wr0[j * DD + (k - DD)];
        g_Wt1[i] = (k < DD) ? Wl1[j * DD + k] : Wr1[j * DD + (k - DD)];
    }
    if (i < NN) g_deg[i] = 0;
}

// Decode edge list to int32 + degree histogram + within-bucket rank.
__global__ void convert_count(const void* __restrict__ ei_raw, int E) {
    int e = blockIdx.x * blockDim.x + threadIdx.x;
    if (e >= E) return;
    int s, d;
    if (g_is64) {
        const long long* ei = (const long long*)ei_raw;
        s = (int)ei[e];
        d = (int)ei[E + e];
    } else {
        const int* ei = (const int*)ei_raw;
        s = ei[e];
        d = ei[E + e];
    }
    g_src[e] = s;
    g_dst[e] = d;
    g_rank[e] = atomicAdd(&g_deg[d], 1);
}

// scan step 1: per-block exclusive scan + block sums
__global__ void scan1() {
    __shared__ int sh[SCAN_B];
    int i = blockIdx.x * SCAN_B + threadIdx.x;
    int v = (i < NN) ? g_deg[i] : 0;
    sh[threadIdx.x] = v;
    __syncthreads();
#pragma unroll
    for (int off = 1; off < SCAN_B; off <<= 1) {
        int t = (threadIdx.x >= off) ? sh[threadIdx.x - off] : 0;
        __syncthreads();
        sh[threadIdx.x] += t;
        __syncthreads();
    }
    int incl = sh[threadIdx.x];
    if (i < NN) g_rowptr[i] = incl - v;
    if (threadIdx.x == SCAN_B - 1) g_bsum[blockIdx.x] = incl;
}

// scan step 2: every block scans the block sums in parallel, applies offset.
__global__ void scan_apply() {
    __shared__ int sh[SCAN_B];
    int v = (threadIdx.x < NBLK) ? g_bsum[threadIdx.x] : 0;
    sh[threadIdx.x] = v;
    __syncthreads();
#pragma unroll
    for (int off = 1; off < SCAN_B; off <<= 1) {
        int t = (threadIdx.x >= off) ? sh[threadIdx.x - off] : 0;
        __syncthreads();
        sh[threadIdx.x] += t;
        __syncthreads();
    }
    int off = (blockIdx.x > 0) ? sh[blockIdx.x - 1] : 0;
    int i = blockIdx.x * SCAN_B + threadIdx.x;
    if (i < NN)
        g_rowptr[i] += off;
}

// CSR fill: atomic-free via precomputed ranks.
__global__ void fill_csr(int E) {
    int e = blockIdx.x * blockDim.x + threadIdx.x;
    if (e >= E) return;
    g_col[g_rowptr[g_dst[e]] + g_rank[e]] = g_src[e];
}

// ---- pull-style aggregation: 16 threads per node, atomic-free ----
__global__ void aggregate(const float* __restrict__ x, int useH) {
    int gid = blockIdx.x * blockDim.x + threadIdx.x;
    int node = gid >> 4;
    int lane = gid & 15;
    if (node >= NN) return;
    const float* xin = useH ? g_h : x;

    int beg = g_rowptr[node];
    int deg = g_deg[node];

    float4 acc = make_float4(0.f, 0.f, 0.f, 0.f);
    int j = 0;
    for (; j + 4 <= deg; j += 4) {
        int i0 = __ldg(g_col + beg + j + 0);
        int i1 = __ldg(g_col + beg + j + 1);
        int i2 = __ldg(g_col + beg + j + 2);
        int i3 = __ldg(g_col + beg + j + 3);
        float4 v0 = __ldg(reinterpret_cast<const float4*>(xin + (size_t)i0 * DD) + lane);
        float4 v1 = __ldg(reinterpret_cast<const float4*>(xin + (size_t)i1 * DD) + lane);
        float4 v2 = __ldg(reinterpret_cast<const float4*>(xin + (size_t)i2 * DD) + lane);
        float4 v3 = __ldg(reinterpret_cast<const float4*>(xin + (size_t)i3 * DD) + lane);
        acc.x += v0.x; acc.y += v0.y; acc.z += v0.z; acc.w += v0.w;
        acc.x += v1.x; acc.y += v1.y; acc.z += v1.z; acc.w += v1.w;
        acc.x += v2.x; acc.y += v2.y; acc.z += v2.z; acc.w += v2.w;
        acc.x += v3.x; acc.y += v3.y; acc.z += v3.z; acc.w += v3.w;
    }
    for (; j < deg; j++) {
        int i0 = __ldg(g_col + beg + j);
        float4 v0 = __ldg(reinterpret_cast<const float4*>(xin + (size_t)i0 * DD) + lane);
        acc.x += v0.x; acc.y += v0.y; acc.z += v0.z; acc.w += v0.w;
    }
    float sc = 1.f / (float)max(deg, 1);
    acc.x *= sc; acc.y *= sc; acc.z *= sc; acc.w *= sc;
    reinterpret_cast<float4*>(g_agg + (size_t)node * DD)[lane] = acc;
}

// ---- tf32 helpers ----
__device__ __forceinline__ uint32_t f2tf32(float f) {
    uint32_t r;
    asm("cvt.rna.tf32.f32 %0, %1;" : "=r"(r) : "f"(f));
    return r;
}
__device__ __forceinline__ void mma_tf32(float c[4], uint32_t a0, uint32_t a1,
                                         uint32_t a2, uint32_t a3,
                                         uint32_t b0, uint32_t b1) {
    asm volatile(
        "mma.sync.aligned.m16n8k8.row.col.f32.tf32.tf32.f32 "
        "{%0,%1,%2,%3}, {%4,%5,%6,%7}, {%8,%9}, {%0,%1,%2,%3};"
        : "+f"(c[0]), "+f"(c[1]), "+f"(c[2]), "+f"(c[3])
        : "r"(a0), "r"(a1), "r"(a2), "r"(a3), "r"(b0), "r"(b1));
}

// Fused: C[64 nodes][64 out] = A[64][128] * B[128][64] + bias (+ ReLU)
// Tensor-core version: 3xTF32 (hi/lo split) for fp32-grade accuracy.
// 8 warps: wm = wid>>1 (16-row M tile), wn = wid&1 (32-col N tile).
// sA[m][k] stride 68, sB[k][n] stride 72 -> conflict-free fragment LDS.
#define SA_S 68
#define SB_S 72
__global__ __launch_bounds__(256) void gemm_combine(const float* __restrict__ x,
                                                    int useH, int useW1,
                                                    const float* __restrict__ bias,
                                                    float* __restrict__ dout,
                                                    int writeH, int doRelu) {
    __shared__ __align__(16) float sA[64 * SA_S];
    __shared__ __align__(16) float sB[64 * SB_S];
    const float* xin = useH ? g_h : x;
    const float* Wt = useW1 ? g_Wt1 : g_Wt0;
    float* outp = writeH ? g_h : dout;

    int t = threadIdx.x;
    int m0 = blockIdx.x * 64;
    int wid = t >> 5;
    int lane = t & 31;
    int wm = wid >> 1;          // 0..3 -> M sub-tile of 16
    int wn = wid & 1;           // 0..1 -> N sub-tile of 32
    int g = lane >> 2;          // fragment group row 0..7
    int t4 = lane & 3;          // fragment col 0..3

    float c[4][4];              // [n-tile][c-frag]
#pragma unroll
    for (int i = 0; i < 4; i++)
#pragma unroll
        for (int j = 0; j < 4; j++) c[i][j] = 0.f;

    int lm = t >> 2;            // loader: row 0..63
    int lq = t & 3;             // loader: 16-float chunk 0..3
    int node_l = m0 + lm;

#pragma unroll
    for (int kt = 0; kt < 2; kt++) {
        // Load A half: sA[m][k] natural layout, direct float4 row copies
        {
            const float* srcRow = (kt == 0) ? (g_agg + (size_t)node_l * DD)
                                            : (xin + (size_t)node_l * DD);
#pragma unroll
            for (int f = 0; f < 4; f++) {
                float4 v = make_float4(0.f, 0.f, 0.f, 0.f);
                if (node_l < NN)
                    v = *reinterpret_cast<const float4*>(srcRow + lq * 16 + f * 4);
                *reinterpret_cast<float4*>(sA + lm * SA_S + lq * 16 + f * 4) = v;
            }
        }
        // Load B half: sB[k][n] from pre-transposed Wt[k][j]
        {
            const float* srcRow = Wt + (size_t)(kt * 64 + lm) * 64;
#pragma unroll
            for (int f = 0; f < 4; f++) {
                float4 v = *reinterpret_cast<const float4*>(srcRow + lq * 16 + f * 4);
                *reinterpret_cast<float4*>(sB + lm * SB_S + lq * 16 + f * 4) = v;
            }
        }
        __syncthreads();

#pragma unroll
        for (int ks = 0; ks < 8; ks++) {
            int kk = ks * 8;
            // A fragments (m16 x k8), orig -> hi/lo
            const float* Abase = sA + (wm * 16 + g) * SA_S + kk + t4;
            float av0 = Abase[0];
            float av1 = Abase[8 * SA_S];
            float av2 = Abase[4];
            float av3 = Abase[8 * SA_S + 4];
            uint32_t ah0 = f2tf32(av0), ah1 = f2tf32(av1), ah2 = f2tf32(av2), ah3 = f2tf32(av3);
            uint32_t al0 = f2tf32(av0 - __uint_as_float(ah0));
            uint32_t al1 = f2tf32(av1 - __uint_as_float(ah1));
            uint32_t al2 = f2tf32(av2 - __uint_as_float(ah2));
            uint32_t al3 = f2tf32(av3 - __uint_as_float(ah3));

#pragma unroll
            for (int nt = 0; nt < 4; nt++) {
                int n0 = wn * 32 + nt * 8;
                float bv0 = sB[(kk + t4) * SB_S + n0 + g];
                float bv1 = sB[(kk + t4 + 4) * SB_S + n0 + g];
                uint32_t bh0 = f2tf32(bv0), bh1 = f2tf32(bv1);
                uint32_t bl0 = f2tf32(bv0 - __uint_as_float(bh0));
                uint32_t bl1 = f2tf32(bv1 - __uint_as_float(bh1));
                mma_tf32(c[nt], ah0, ah1, ah2, ah3, bh0, bh1);
                mma_tf32(c[nt], ah0, ah1, ah2, ah3, bl0, bl1);
                mma_tf32(c[nt], al0, al1, al2, al3, bh0, bh1);
            }
        }
        __syncthreads();
    }

    // Epilogue: c-frag mapping: c0 (row=g, col=t4*2), c1 (col+1), c2 (row+8), c3.
#pragma unroll
    for (int nt = 0; nt < 4; nt++) {
        int col = wn * 32 + nt * 8 + t4 * 2;
        float b0 = bias[col];
        float b1 = bias[col + 1];
        int row0 = m0 + wm * 16 + g;
        int row1 = row0 + 8;
        float2 o0 = make_float2(c[nt][0] + b0, c[nt][1] + b1);
        float2 o1 = make_float2(c[nt][2] + b0, c[nt][3] + b1);
        if (doRelu) {
            o0.x = fmaxf(o0.x, 0.f); o0.y = fmaxf(o0.y, 0.f);
            o1.x = fmaxf(o1.x, 0.f); o1.y = fmaxf(o1.y, 0.f);
        }
        if (row0 < NN)
            *reinterpret_cast<float2*>(outp + (size_t)row0 * DD + col) = o0;
        if (row1 < NN)
            *reinterpret_cast<float2*>(outp + (size_t)row1 * DD + col) = o1;
    }
}

extern "C" void kernel_launch(void* const* d_in, const int* in_sizes, int n_in,
                              void* d_out, int out_size) {
    const float* x        = (const float*)d_in[0];
    const void* ei        = d_in[1];
    const float* Wl0      = (const float*)d_in[2];
    const float* bl0      = (const float*)d_in[3];
    const float* Wr0      = (const float*)d_in[4];
    const float* Wl1      = (const float*)d_in[5];
    const float* bl1      = (const float*)d_in[6];
    const float* Wr1      = (const float*)d_in[7];
    float* out = (float*)d_out;

    int E = in_sizes[1] / 2;

    int edgeBlocks = (E + 255) / 256;
    int aggBlocks = (NN * 16 + 255) / 256;
    int gemmBlocks = (NN + 63) / 64;

    setup_kernel<<<(NN + 255) / 256, 256>>>(Wl0, Wr0, Wl1, Wr1, (const long long*)ei);

    // CSR build (shared by both layers)
    convert_count<<<edgeBlocks, 256>>>(ei, E);
    scan1<<<NBLK, SCAN_B>>>();
    scan_apply<<<NBLK, SCAN_B>>>();
    fill_csr<<<edgeBlocks, 256>>>(E);

    // Layer 0
    aggregate<<<aggBlocks, 256>>>(x, /*useH=*/0);
    gemm_combine<<<gemmBlocks, 256>>>(x, /*useH=*/0, /*useW1=*/0, bl0, out,
                                      /*writeH=*/1, /*doRelu=*/1);

    // Layer 1
    aggregate<<<aggBlocks, 256>>>(x, /*useH=*/1);
    gemm_combine<<<gemmBlocks, 256>>>(x, /*useH=*/1, /*useW1=*/1, bl1, out,
                                      /*writeH=*/0, /*doRelu=*/0);
}

// round 11
// speedup vs baseline: 1.8027x; 1.0945x over previous
#include <cuda_runtime.h>
#include <cstdint>

#define NN 50000
#define DD 64
#define MAXE 1600000
#define SCAN_B 256
#define NBLK ((NN + SCAN_B - 1) / SCAN_B)

// Scratch (device globals; no allocations allowed)
__device__ __align__(16) float g_agg[NN * DD];     // normalized mean-agg buffer
__device__ __align__(16) float g_h[NN * DD];       // layer-0 output
__device__ int g_is64;                             // edge-index dtype flag
__device__ int g_deg[NN];                          // in-degree (by dst)
__device__ int g_rowptr[NN];                       // CSR row starts
__device__ int g_col[MAXE];                        // CSR column (src) indices
__device__ int g_src[MAXE];                        // decoded int32 src
__device__ int g_dst[MAXE];                        // decoded int32 dst
__device__ int g_rank[MAXE];                       // within-bucket rank per edge
__device__ int g_bsum[NBLK];                       // scan block sums
// B fragments in tf32 hi/lo, fragment order: [kt][ks][ntile][lane] -> (bh0,bh1,bl0,bl1)
__device__ __align__(16) uint4 g_Bf0[2 * 8 * 8 * 32];
__device__ __align__(16) uint4 g_Bf1[2 * 8 * 8 * 32];

__device__ __forceinline__ uint32_t f2tf32(float f) {
    uint32_t r;
    asm("cvt.rna.tf32.f32 %0, %1;" : "=r"(r) : "f"(f));
    return r;
}

// prep B fragments + zero degree counters + dtype detect, one launch
__global__ void setup_kernel(const float* __restrict__ Wl0, const float* __restrict__ Wr0,
                             const float* __restrict__ Wl1, const float* __restrict__ Wr1,
                             const long long* __restrict__ ei) {
    int i = blockIdx.x * blockDim.x + threadIdx.x;
    if (i == 0) {
        long long acc = 0;
#pragma unroll
        for (int k = 0; k < 8; k++) acc |= (ei[k] >> 32);
        g_is64 = (acc == 0) ? 1 : 0;
    }
    if (i < 2 * 8 * 8 * 32) {
        int lane = i & 31;
        int ntg = (i >> 5) & 7;
        int ks = (i >> 8) & 7;
        int kt = i >> 11;
        int t4 = lane & 3;
        int g = lane >> 2;
        int n = ntg * 8 + g;
        int k0 = kt * 64 + ks * 8 + t4;   // 0..127
        int k1 = k0 + 4;
        // B[k][n]: k<64 -> Wl[n][k], k>=64 -> Wr[n][k-64]
        float w0a = (k0 < DD) ? Wl0[n * DD + k0] : Wr0[n * DD + (k0 - DD)];
        float w1a = (k1 < DD) ? Wl0[n * DD + k1] : Wr0[n * DD + (k1 - DD)];
        float w0b = (k0 < DD) ? Wl1[n * DD + k0] : Wr1[n * DD + (k0 - DD)];
        float w1b = (k1 < DD) ? Wl1[n * DD + k1] : Wr1[n * DD + (k1 - DD)];
        uint32_t h0, h1;
        h0 = f2tf32(w0a); h1 = f2tf32(w1a);
        g_Bf0[i] = make_uint4(h0, h1, f2tf32(w0a - __uint_as_float(h0)),
                                       f2tf32(w1a - __uint_as_float(h1)));
        h0 = f2tf32(w0b); h1 = f2tf32(w1b);
        g_Bf1[i] = make_uint4(h0, h1, f2tf32(w0b - __uint_as_float(h0)),
                                       f2tf32(w1b - __uint_as_float(h1)));
    }
    if (i < NN) g_deg[i] = 0;
}

// Decode edge list to int32 + degree histogram + within-bucket rank.
__global__ void convert_count(const void* __restrict__ ei_raw, int E) {
    int e = blockIdx.x * blockDim.x + threadIdx.x;
    if (e >= E) return;
    int s, d;
    if (g_is64) {
        const long long* ei = (const long long*)ei_raw;
        s = (int)ei[e];
        d = (int)ei[E + e];
    } else {
        const int* ei = (const int*)ei_raw;
        s = ei[e];
        d = ei[E + e];
    }
    g_src[e] = s;
    g_dst[e] = d;
    g_rank[e] = atomicAdd(&g_deg[d], 1);
}

// scan step 1: per-block exclusive scan + block sums
__global__ void scan1() {
    __shared__ int sh[SCAN_B];
    int i = blockIdx.x * SCAN_B + threadIdx.x;
    int v = (i < NN) ? g_deg[i] : 0;
    sh[threadIdx.x] = v;
    __syncthreads();
#pragma unroll
    for (int off = 1; off < SCAN_B; off <<= 1) {
        int t = (threadIdx.x >= off) ? sh[threadIdx.x - off] : 0;
        __syncthreads();
        sh[threadIdx.x] += t;
        __syncthreads();
    }
    int incl = sh[threadIdx.x];
    if (i < NN) g_rowptr[i] = incl - v;
    if (threadIdx.x == SCAN_B - 1) g_bsum[blockIdx.x] = incl;
}

// scan step 2: every block scans the block sums in parallel, applies offset.
__global__ void scan_apply() {
    __shared__ int sh[SCAN_B];
    int v = (threadIdx.x < NBLK) ? g_bsum[threadIdx.x] : 0;
    sh[threadIdx.x] = v;
    __syncthreads();
#pragma unroll
    for (int off = 1; off < SCAN_B; off <<= 1) {
        int t = (threadIdx.x >= off) ? sh[threadIdx.x - off] : 0;
        __syncthreads();
        sh[threadIdx.x] += t;
        __syncthreads();
    }
    int off = (blockIdx.x > 0) ? sh[blockIdx.x - 1] : 0;
    int i = blockIdx.x * SCAN_B + threadIdx.x;
    if (i < NN)
        g_rowptr[i] += off;
}

// CSR fill: atomic-free via precomputed ranks.
__global__ void fill_csr(int E) {
    int e = blockIdx.x * blockDim.x + threadIdx.x;
    if (e >= E) return;
    g_col[g_rowptr[g_dst[e]] + g_rank[e]] = g_src[e];
}

// ---- pull-style aggregation: 16 threads per node, atomic-free ----
__global__ void aggregate(const float* __restrict__ x, int useH) {
    int gid = blockIdx.x * blockDim.x + threadIdx.x;
    int node = gid >> 4;
    int lane = gid & 15;
    if (node >= NN) return;
    const float* xin = useH ? g_h : x;

    int beg = g_rowptr[node];
    int deg = g_deg[node];

    float4 acc = make_float4(0.f, 0.f, 0.f, 0.f);
    int j = 0;
    for (; j + 4 <= deg; j += 4) {
        int i0 = __ldg(g_col + beg + j + 0);
        int i1 = __ldg(g_col + beg + j + 1);
        int i2 = __ldg(g_col + beg + j + 2);
        int i3 = __ldg(g_col + beg + j + 3);
        float4 v0 = __ldg(reinterpret_cast<const float4*>(xin + (size_t)i0 * DD) + lane);
        float4 v1 = __ldg(reinterpret_cast<const float4*>(xin + (size_t)i1 * DD) + lane);
        float4 v2 = __ldg(reinterpret_cast<const float4*>(xin + (size_t)i2 * DD) + lane);
        float4 v3 = __ldg(reinterpret_cast<const float4*>(xin + (size_t)i3 * DD) + lane);
        acc.x += v0.x; acc.y += v0.y; acc.z += v0.z; acc.w += v0.w;
        acc.x += v1.x; acc.y += v1.y; acc.z += v1.z; acc.w += v1.w;
        acc.x += v2.x; acc.y += v2.y; acc.z += v2.z; acc.w += v2.w;
        acc.x += v3.x; acc.y += v3.y; acc.z += v3.z; acc.w += v3.w;
    }
    for (; j < deg; j++) {
        int i0 = __ldg(g_col + beg + j);
        float4 v0 = __ldg(reinterpret_cast<const float4*>(xin + (size_t)i0 * DD) + lane);
        acc.x += v0.x; acc.y += v0.y; acc.z += v0.z; acc.w += v0.w;
    }
    float sc = 1.f / (float)max(deg, 1);
    acc.x *= sc; acc.y *= sc; acc.z *= sc; acc.w *= sc;
    reinterpret_cast<float4*>(g_agg + (size_t)node * DD)[lane] = acc;
}

__device__ __forceinline__ void mma_tf32(float c[4], uint32_t a0, uint32_t a1,
                                         uint32_t a2, uint32_t a3,
                                         uint32_t b0, uint32_t b1) {
    asm volatile(
        "mma.sync.aligned.m16n8k8.row.col.f32.tf32.tf32.f32 "
        "{%0,%1,%2,%3}, {%4,%5,%6,%7}, {%8,%9}, {%0,%1,%2,%3};"
        : "+f"(c[0]), "+f"(c[1]), "+f"(c[2]), "+f"(c[3])
        : "r"(a0), "r"(a1), "r"(a2), "r"(a3), "r"(b0), "r"(b1));
}

// Fused: C[64 nodes][64 out] = A[64][128] * B[128][64] + bias (+ ReLU)
// 3xTF32; A pre-split to hi/lo smem at load; B fragments pre-split in global
// fragment order -> inner loop: 8 LDS + 4 LDG.128 + 12 MMA per k-step.
#define SA_S 68
__global__ __launch_bounds__(256) void gemm_combine(const float* __restrict__ x,
                                                    int useH, int useW1,
                                                    const float* __restrict__ bias,
                                                    float* __restrict__ dout,
                                                    int writeH, int doRelu) {
    __shared__ __align__(16) uint32_t sAh[64 * SA_S];
    __shared__ __align__(16) uint32_t sAl[64 * SA_S];
    const float* xin = useH ? g_h : x;
    const uint4* Bf = useW1 ? g_Bf1 : g_Bf0;
    float* outp = writeH ? g_h : dout;

    int t = threadIdx.x;
    int m0 = blockIdx.x * 64;
    int wid = t >> 5;
    int lane = t & 31;
    int wm = wid >> 1;          // 0..3 -> M sub-tile of 16
    int wn = wid & 1;           // 0..1 -> N sub-tile of 32
    int g = lane >> 2;          // fragment group row 0..7
    int t4 = lane & 3;          // fragment col 0..3

    float c[4][4];
#pragma unroll
    for (int i = 0; i < 4; i++)
#pragma unroll
        for (int j = 0; j < 4; j++) c[i][j] = 0.f;

    int lm = t >> 2;            // loader: row 0..63
    int lq = t & 3;             // loader: 16-float chunk 0..3
    int node_l = m0 + lm;

#pragma unroll
    for (int kt = 0; kt < 2; kt++) {
        // Load + split A half into hi/lo tf32 smem
        {
            const float* srcRow = (kt == 0) ? (g_agg + (size_t)node_l * DD)
                                            : (xin + (size_t)node_l * DD);
#pragma unroll
            for (int f = 0; f < 4; f++) {
                float4 v = make_float4(0.f, 0.f, 0.f, 0.f);
                if (node_l < NN)
                    v = *reinterpret_cast<const float4*>(srcRow + lq * 16 + f * 4);
                uint4 h, l;
                h.x = f2tf32(v.x); l.x = f2tf32(v.x - __uint_as_float(h.x));
                h.y = f2tf32(v.y); l.y = f2tf32(v.y - __uint_as_float(h.y));
                h.z = f2tf32(v.z); l.z = f2tf32(v.z - __uint_as_float(h.z));
                h.w = f2tf32(v.w); l.w = f2tf32(v.w - __uint_as_float(h.w));
                int o = lm * SA_S + lq * 16 + f * 4;
                *reinterpret_cast<uint4*>(sAh + o) = h;
                *reinterpret_cast<uint4*>(sAl + o) = l;
            }
        }
        __syncthreads();

#pragma unroll
        for (int ks = 0; ks < 8; ks++) {
            int kk = ks * 8;
            const uint32_t* Ah = sAh + (wm * 16 + g) * SA_S + kk + t4;
            const uint32_t* Al = sAl + (wm * 16 + g) * SA_S + kk + t4;
            uint32_t ah0 = Ah[0], ah1 = Ah[8 * SA_S], ah2 = Ah[4], ah3 = Ah[8 * SA_S + 4];
            uint32_t al0 = Al[0], al1 = Al[8 * SA_S], al2 = Al[4], al3 = Al[8 * SA_S + 4];

            const uint4* Brow = Bf + ((kt * 8 + ks) * 8 + wn * 4) * 32 + lane;
#pragma unroll
            for (int nt = 0; nt < 4; nt++) {
                uint4 b = __ldg(Brow + nt * 32);
                mma_tf32(c[nt], ah0, ah1, ah2, ah3, b.x, b.y);
                mma_tf32(c[nt], ah0, ah1, ah2, ah3, b.z, b.w);
                mma_tf32(c[nt], al0, al1, al2, al3, b.x, b.y);
            }
        }
        __syncthreads();
    }

    // Epilogue: c0 (row=g, col=t4*2), c1 (col+1), c2 (row+8), c3 (row+8,col+1).
#pragma unroll
    for (int nt = 0; nt < 4; nt++) {
        int col = wn * 32 + nt * 8 + t4 * 2;
        float b0 = bias[col];
        float b1 = bias[col + 1];
        int row0 = m0 + wm * 16 + g;
        int row1 = row0 + 8;
        float2 o0 = make_float2(c[nt][0] + b0, c[nt][1] + b1);
        float2 o1 = make_float2(c[nt][2] + b0, c[nt][3] + b1);
        if (doRelu) {
            o0.x = fmaxf(o0.x, 0.f); o0.y = fmaxf(o0.y, 0.f);
            o1.x = fmaxf(o1.x, 0.f); o1.y = fmaxf(o1.y, 0.f);
        }
        if (row0 < NN)
            *reinterpret_cast<float2*>(outp + (size_t)row0 * DD + col) = o0;
        if (row1 < NN)
            *reinterpret_cast<float2*>(outp + (size_t)row1 * DD + col) = o1;
    }
}

extern "C" void kernel_launch(void* const* d_in, const int* in_sizes, int n_in,
                              void* d_out, int out_size) {
    const float* x        = (const float*)d_in[0];
    const void* ei        = d_in[1];
    const float* Wl0      = (const float*)d_in[2];
    const float* bl0      = (const float*)d_in[3];
    const float* Wr0      = (const float*)d_in[4];
    const float* Wl1      = (const float*)d_in[5];
    const float* bl1      = (const float*)d_in[6];
    const float* Wr1      = (const float*)d_in[7];
    float* out = (float*)d_out;

    int E = in_sizes[1] / 2;

    int edgeBlocks = (E + 255) / 256;
    int aggBlocks = (NN * 16 + 255) / 256;
    int gemmBlocks = (NN + 63) / 64;

    setup_kernel<<<(NN + 255) / 256, 256>>>(Wl0, Wr0, Wl1, Wr1, (const long long*)ei);

    // CSR build (shared by both layers)
    convert_count<<<edgeBlocks, 256>>>(ei, E);
    scan1<<<NBLK, SCAN_B>>>();
    scan_apply<<<NBLK, SCAN_B>>>();
    fill_csr<<<edgeBlocks, 256>>>(E);

    // Layer 0
    aggregate<<<aggBlocks, 256>>>(x, /*useH=*/0);
    gemm_combine<<<gemmBlocks, 256>>>(x, /*useH=*/0, /*useW1=*/0, bl0, out,
                                      /*writeH=*/1, /*doRelu=*/1);

    // Layer 1
    aggregate<<<aggBlocks, 256>>>(x, /*useH=*/1);
    gemm_combine<<<gemmBlocks, 256>>>(x, /*useH=*/1, /*useW1=*/1, bl1, out,
                                      /*writeH=*/0, /*doRelu=*/0);
}